// round 9
// baseline (speedup 1.0000x reference)
#include <cuda_runtime.h>
#include <cstdint>

#define Tt   2048
#define Hd   2048
#define Ee   32
#define DF   1024
#define DS   4096
#define TOPK 6
#define NGROUP 8
#define GSZ  4
#define TKG  4
#define SCALEF 2.5f

// ---------------- static device scratch (no allocations allowed) ----------------
__device__ float g_combine[Tt * Ee];
__device__ int   g_cnt[Ee];
__device__ int   g_off[Ee];
__device__ int   g_tok[Ee * Tt];
__device__ float g_act[(size_t)Tt * TOPK * DF];
__device__ float g_s1[(size_t)Tt * DS];

// ---------------- small kernels ----------------
__global__ void zero_cnt_kernel() {
    if (threadIdx.x < Ee) g_cnt[threadIdx.x] = 0;
}
__global__ void offs_kernel() {
    if (threadIdx.x == 0) {
        int r = 0;
        for (int e = 0; e < Ee; e++) { g_off[e] = r; r += g_cnt[e]; }
    }
}

// ---------------- router: one block (128 thr) per token ----------------
__global__ void router_kernel(const float* __restrict__ x,
                              const float* __restrict__ rw,
                              const float* __restrict__ rb) {
    __shared__ __align__(16) float xs[Hd];
    __shared__ float logits[Ee];
    const int t   = blockIdx.x;
    const int tid = threadIdx.x;
    const float* xt = x + (size_t)t * Hd;

    for (int i = tid; i < Hd / 4; i += 128)
        ((float4*)xs)[i] = ((const float4*)xt)[i];
    __syncthreads();

    const int lane = tid & 31, wid = tid >> 5;
    for (int ei = 0; ei < 8; ei++) {
        int e = wid * 8 + ei;
        const float4* wr = (const float4*)(rw + (size_t)e * Hd);
        float s = 0.f;
        for (int i = lane; i < Hd / 4; i += 32) {
            float4 a = ((const float4*)xs)[i];
            float4 b = wr[i];
            s += a.x * b.x + a.y * b.y + a.z * b.z + a.w * b.w;
        }
        #pragma unroll
        for (int o = 16; o; o >>= 1) s += __shfl_xor_sync(0xffffffffu, s, o);
        if (lane == 0) logits[e] = s;
    }
    __syncthreads();

    if (tid < Ee) g_combine[t * Ee + tid] = 0.f;
    __syncthreads();

    if (tid == 0) {
        float sc[Ee], sfc[Ee];
        for (int e = 0; e < Ee; e++) {
            float v = 1.f / (1.f + expf(-logits[e]));
            sc[e]  = v;
            sfc[e] = v + rb[e];
        }
        float gs[NGROUP];
        for (int g = 0; g < NGROUP; g++) {
            float m1 = -1e30f, m2 = -1e30f;
            for (int j = 0; j < GSZ; j++) {
                float v = sfc[g * GSZ + j];
                if (v > m1) { m2 = m1; m1 = v; }
                else if (v > m2) m2 = v;
            }
            gs[g] = m1 + m2;
        }
        bool gsel[NGROUP];
        for (int g = 0; g < NGROUP; g++) gsel[g] = false;
        for (int k = 0; k < TKG; k++) {
            int bi = -1; float bv = -1e30f;
            for (int g = 0; g < NGROUP; g++)
                if (!gsel[g] && gs[g] > bv) { bv = gs[g]; bi = g; }
            gsel[bi] = true;
        }
        float masked[Ee];
        for (int e = 0; e < Ee; e++) masked[e] = gsel[e / GSZ] ? sfc[e] : 0.0f;

        int   idx[TOPK]; float tw[TOPK]; float tsum = 0.f;
        for (int k = 0; k < TOPK; k++) {
            int bi = 0; float bv = -1e30f;
            for (int e = 0; e < Ee; e++)
                if (masked[e] > bv) { bv = masked[e]; bi = e; }
            masked[bi] = -1e30f;
            idx[k] = bi; tw[k] = sc[bi]; tsum += sc[bi];
        }
        float inv = SCALEF / (tsum + 1e-20f);
        for (int k = 0; k < TOPK; k++) {
            int e = idx[k];
            g_combine[t * Ee + e] = tw[k] * inv;
            int slot = atomicAdd(&g_cnt[e], 1);
            g_tok[e * Tt + slot] = t;
        }
    }
}

// ------- tf32 warp-mma GEMM: 128x256x32 block, 16 warps, 64x32 warp tile, cp.async x3 -------
#define BM 128
#define BN 256
#define BK 32
#define STAGES 3
#define NTHR 512
#define ASTR 36          // floats per A row (conflict-free frag reads)
#define BSTR 264         // floats per B row (conflict-free frag reads)
#define ASTAGE (BM * ASTR)   // 4608 floats
#define BSTAGE (BK * BSTR)   // 8448 floats
#define SMEM_BYTES (STAGES * (ASTAGE + BSTAGE) * 4)   // 156672

__device__ __forceinline__ uint32_t f2tf32(float f) {
    uint32_t r;
    asm("cvt.rna.tf32.f32 %0, %1;" : "=r"(r) : "f"(f));
    return r;
}

__device__ __forceinline__ void mma_tf32(float (&c)[4], const uint32_t (&a)[4],
                                         const uint32_t (&b)[2]) {
    asm volatile(
        "mma.sync.aligned.m16n8k8.row.col.f32.tf32.tf32.f32 "
        "{%0,%1,%2,%3}, {%4,%5,%6,%7}, {%8,%9}, {%0,%1,%2,%3};\n"
        : "+f"(c[0]), "+f"(c[1]), "+f"(c[2]), "+f"(c[3])
        : "r"(a[0]), "r"(a[1]), "r"(a[2]), "r"(a[3]), "r"(b[0]), "r"(b[1]));
}

__device__ __forceinline__ void cp16(uint32_t dst, const void* src, bool valid) {
    int sz = valid ? 16 : 0;
    asm volatile("cp.async.cg.shared.global [%0], [%1], 16, %2;\n"
                 :: "r"(dst), "l"(src), "r"(sz));
}
__device__ __forceinline__ void cp_commit() {
    asm volatile("cp.async.commit_group;\n");
}
__device__ __forceinline__ void cp_wait() {
    asm volatile("cp.async.wait_group %0;\n" :: "n"(STAGES - 2));
}

__device__ __forceinline__ void red2(float* p, float v0, float v1) {
    asm volatile("red.global.add.v2.f32 [%0], {%1,%2};\n" :: "l"(p), "f"(v0), "f"(v1));
}

// MODE 0: shared up   (A = x,        B = shared_up,   C = g_s1,  relu2)
// MODE 1: shared down (A = g_s1,     B = shared_down, C = out,   plain store)
// MODE 2: moe up      (A = x gather, B = w_up[e],     C = g_act, relu2*combine)
// MODE 3: moe down    (A = g_act,    B = w_down[e],   C = out,   atomic scatter)
template <int MODE>
__global__ __launch_bounds__(NTHR, 1)
void gemm_kernel(const float* __restrict__ Aglob, const float* __restrict__ Bglob,
                 float* __restrict__ Cglob) {
    extern __shared__ float smem[];
    float* As = smem;
    float* Bs = smem + STAGES * ASTAGE;

    constexpr int Kk = (MODE == 1) ? DS : ((MODE == 3) ? DF : Hd);
    constexpr int Nn = (MODE == 0) ? DS : ((MODE == 2) ? DF : Hd);

    const int tid = threadIdx.x;
    const int e  = (MODE >= 2) ? blockIdx.z : 0;
    const int m0 = blockIdx.y * BM;
    const int n0 = blockIdx.x * BN;

    int ne = Tt, off_e = 0;
    const float* Ap = Aglob;
    const float* Bp = Bglob;
    if (MODE == 1) Ap = g_s1;
    if (MODE == 3) Ap = g_act;
    if (MODE >= 2) {
        ne = g_cnt[e];
        if (m0 >= ne) return;
        off_e = g_off[e];
        Bp = Bglob + (size_t)e * Kk * Nn;
    }

    // ---- loader mapping (cp.async, 16B chunks, 512 threads) ----
    // A: 1024 chunks -> 2/thread; row = (tid>>3) + 64*i, col4 = (tid&7)*4
    const int ar0 = tid >> 3;           // 0..63
    const int ac4 = (tid & 7) * 4;
    const float* aSrc[2];
    #pragma unroll
    for (int i = 0; i < 2; i++) {
        int r = m0 + ar0 + i * 64;
        int grow;
        if (MODE == 2)      grow = (r < ne) ? g_tok[e * Tt + r] : -1;
        else if (MODE == 3) grow = (r < ne) ? (off_e + r) : -1;
        else                grow = r;
        aSrc[i] = (grow >= 0) ? (Ap + (size_t)grow * Kk + ac4) : nullptr;
    }
    uint32_t aDst = (uint32_t)__cvta_generic_to_shared(As) + (ar0 * ASTR + ac4) * 4;

    // B: 2048 chunks -> 4/thread; k = (tid>>6) + 8*i, col4 = (tid&63)*4
    const int br0 = tid >> 6;           // 0..7
    const int bc4 = (tid & 63) * 4;
    const float* bSrc = Bp + (size_t)br0 * Nn + n0 + bc4;
    uint32_t bDst = (uint32_t)__cvta_generic_to_shared(Bs) + (br0 * BSTR + bc4) * 4;

    auto issue = [&](int k0, int st) {
        uint32_t ad = aDst + st * (ASTAGE * 4);
        #pragma unroll
        for (int i = 0; i < 2; i++)
            cp16(ad + i * (64 * ASTR * 4),
                 aSrc[i] ? (aSrc[i] + k0) : Ap, aSrc[i] != nullptr);
        uint32_t bd = bDst + st * (BSTAGE * 4);
        const float* bp = bSrc + (size_t)k0 * Nn;
        #pragma unroll
        for (int i = 0; i < 4; i++)
            cp16(bd + i * (8 * BSTR * 4), bp + (size_t)i * 8 * Nn, true);
        cp_commit();
    };

    // ---- warp tiling: 2(m) x 8(n) warps, 64x32 per warp ----
    const int lane = tid & 31, wid = tid >> 5;
    const int qr = lane >> 2, qc = lane & 3;
    const int mb = (wid & 1) * 64;
    const int nb = (wid >> 1) * 32;

    float acc[4][4][4];
    #pragma unroll
    for (int mt = 0; mt < 4; mt++)
        #pragma unroll
        for (int nt = 0; nt < 4; nt++)
            #pragma unroll
            for (int j = 0; j < 4; j++) acc[mt][nt][j] = 0.f;

    const int nk = Kk / BK;

    #pragma unroll
    for (int s = 0; s < STAGES - 1; s++) issue(s * BK, s);

    for (int kb = 0; kb < nk; kb++) {
        cp_wait();
        __syncthreads();   // single barrier per K-tile: stage (kb%3) now safe to read,
                           // and all warps are done with stage ((kb)%3) from 3 iters ago.

        if (kb + STAGES - 1 < nk) issue((kb + STAGES - 1) * BK, (kb + STAGES - 1) % STAGES);
        else                      cp_commit();   // keep group counts aligned

        const uint32_t* Au = (const uint32_t*)(As + (kb % STAGES) * ASTAGE);
        const uint32_t* Bu = (const uint32_t*)(Bs + (kb % STAGES) * BSTAGE);

        #pragma unroll
        for (int ks = 0; ks < BK; ks += 8) {
            uint32_t a[4][4], b[4][2];
            #pragma unroll
            for (int mt = 0; mt < 4; mt++) {
                int r  = mb + mt * 16 + qr;
                int kc = ks + qc;
                a[mt][0] = f2tf32(__uint_as_float(Au[r * ASTR + kc]));
                a[mt][1] = f2tf32(__uint_as_float(Au[(r + 8) * ASTR + kc]));
                a[mt][2] = f2tf32(__uint_as_float(Au[r * ASTR + kc + 4]));
                a[mt][3] = f2tf32(__uint_as_float(Au[(r + 8) * ASTR + kc + 4]));
            }
            #pragma unroll
            for (int nt = 0; nt < 4; nt++) {
                int n = nb + nt * 8 + qr;
                b[nt][0] = f2tf32(__uint_as_float(Bu[(ks + qc) * BSTR + n]));
                b[nt][1] = f2tf32(__uint_as_float(Bu[(ks + qc + 4) * BSTR + n]));
            }
            #pragma unroll
            for (int mt = 0; mt < 4; mt++)
                #pragma unroll
                for (int nt = 0; nt < 4; nt++)
                    mma_tf32(acc[mt][nt], a[mt], b[nt]);
        }
        // NOTE: no trailing __syncthreads — with 3 stages the next write to this
        // stage happens only after the next top-of-loop barrier.
    }

    // -------- epilogue --------
    #pragma unroll
    for (int mt = 0; mt < 4; mt++) {
        int rl0 = mb + mt * 16 + qr;
        int rl1 = rl0 + 8;
        if (MODE == 0 || MODE == 1) {
            int r0 = m0 + rl0, r1 = m0 + rl1;
            float* Cb = (MODE == 0) ? g_s1 : Cglob;
            #pragma unroll
            for (int nt = 0; nt < 4; nt++) {
                int c = n0 + nb + nt * 8 + qc * 2;
                float v0 = acc[mt][nt][0], v1 = acc[mt][nt][1];
                float v2 = acc[mt][nt][2], v3 = acc[mt][nt][3];
                if (MODE == 0) {
                    v0 = fmaxf(v0, 0.f); v0 *= v0;
                    v1 = fmaxf(v1, 0.f); v1 *= v1;
                    v2 = fmaxf(v2, 0.f); v2 *= v2;
                    v3 = fmaxf(v3, 0.f); v3 *= v3;
                }
                *(float2*)&Cb[(size_t)r0 * Nn + c] = make_float2(v0, v1);
                *(float2*)&Cb[(size_t)r1 * Nn + c] = make_float2(v2, v3);
            }
        } else if (MODE == 2) {
            bool va = (m0 + rl0) < ne, vb = (m0 + rl1) < ne;
            int tk0 = va ? g_tok[e * Tt + m0 + rl0] : 0;
            int tk1 = vb ? g_tok[e * Tt + m0 + rl1] : 0;
            float w0 = va ? g_combine[tk0 * Ee + e] : 0.f;
            float w1 = vb ? g_combine[tk1 * Ee + e] : 0.f;
            size_t cr0 = (size_t)(off_e + m0 + rl0) * DF;
            size_t cr1 = (size_t)(off_e + m0 + rl1) * DF;
            #pragma unroll
            for (int nt = 0; nt < 4; nt++) {
                int c = n0 + nb + nt * 8 + qc * 2;
                float v0 = fmaxf(acc[mt][nt][0], 0.f); v0 = v0 * v0 * w0;
                float v1 = fmaxf(acc[mt][nt][1], 0.f); v1 = v1 * v1 * w0;
                float v2 = fmaxf(acc[mt][nt][2], 0.f); v2 = v2 * v2 * w1;
                float v3 = fmaxf(acc[mt][nt][3], 0.f); v3 = v3 * v3 * w1;
                if (va) *(float2*)&g_act[cr0 + c] = make_float2(v0, v1);
                if (vb) *(float2*)&g_act[cr1 + c] = make_float2(v2, v3);
            }
        } else {  // MODE 3: vector atomic scatter into out
            bool va = (m0 + rl0) < ne, vb = (m0 + rl1) < ne;
            int tk0 = va ? g_tok[e * Tt + m0 + rl0] : 0;
            int tk1 = vb ? g_tok[e * Tt + m0 + rl1] : 0;
            #pragma unroll
            for (int nt = 0; nt < 4; nt++) {
                int c = n0 + nb + nt * 8 + qc * 2;
                if (va) red2(&Cglob[(size_t)tk0 * Hd + c], acc[mt][nt][0], acc[mt][nt][1]);
                if (vb) red2(&Cglob[(size_t)tk1 * Hd + c], acc[mt][nt][2], acc[mt][nt][3]);
            }
        }
    }
}

// ---------------- launch ----------------
extern "C" void kernel_launch(void* const* d_in, const int* in_sizes, int n_in,
                              void* d_out, int out_size) {
    const float* x     = (const float*)d_in[0];
    const float* rw    = (const float*)d_in[1];
    const float* rb    = (const float*)d_in[2];
    const float* w_up  = (const float*)d_in[3];
    const float* w_dn  = (const float*)d_in[4];
    const float* s_up  = (const float*)d_in[5];
    const float* s_dn  = (const float*)d_in[6];
    float* out = (float*)d_out;

    cudaFuncSetAttribute(gemm_kernel<0>, cudaFuncAttributeMaxDynamicSharedMemorySize, SMEM_BYTES);
    cudaFuncSetAttribute(gemm_kernel<1>, cudaFuncAttributeMaxDynamicSharedMemorySize, SMEM_BYTES);
    cudaFuncSetAttribute(gemm_kernel<2>, cudaFuncAttributeMaxDynamicSharedMemorySize, SMEM_BYTES);
    cudaFuncSetAttribute(gemm_kernel<3>, cudaFuncAttributeMaxDynamicSharedMemorySize, SMEM_BYTES);

    zero_cnt_kernel<<<1, 32>>>();
    router_kernel<<<Tt, 128>>>(x, rw, rb);
    offs_kernel<<<1, 32>>>();

    // routed up: per-expert gathered GEMM -> g_act
    gemm_kernel<2><<<dim3(DF / BN, Tt / BM, Ee), NTHR, SMEM_BYTES>>>(x, w_up, nullptr);

    // shared expert
    gemm_kernel<0><<<dim3(DS / BN, Tt / BM, 1), NTHR, SMEM_BYTES>>>(x, s_up, nullptr);
    gemm_kernel<1><<<dim3(Hd / BN, Tt / BM, 1), NTHR, SMEM_BYTES>>>(nullptr, s_dn, out);

    // routed down: atomic scatter onto out (after shared wrote it)
    gemm_kernel<3><<<dim3(Hd / BN, Tt / BM, Ee), NTHR, SMEM_BYTES>>>(nullptr, w_dn, out);
}

// round 10
// speedup vs baseline: 1.0897x; 1.0897x over previous
#include <cuda_runtime.h>
#include <cstdint>

#define Tt   2048
#define Hd   2048
#define Ee   32
#define DF   1024
#define DS   4096
#define TOPK 6
#define NGROUP 8
#define GSZ  4
#define TKG  4
#define SCALEF 2.5f

// ---------------- static device scratch (no allocations allowed) ----------------
__device__ float g_combine[Tt * Ee];
__device__ int   g_cnt[Ee];
__device__ int   g_off[Ee];
__device__ int   g_tok[Ee * Tt];
__device__ float g_act[(size_t)Tt * TOPK * DF];
__device__ float g_s1[(size_t)Tt * DS];

// ---------------- small kernels ----------------
__global__ void zero_cnt_kernel() {
    if (threadIdx.x < Ee) g_cnt[threadIdx.x] = 0;
}
__global__ void offs_kernel() {
    if (threadIdx.x == 0) {
        int r = 0;
        for (int e = 0; e < Ee; e++) { g_off[e] = r; r += g_cnt[e]; }
    }
}

// ---------------- router: one block (128 thr) per token ----------------
__global__ void router_kernel(const float* __restrict__ x,
                              const float* __restrict__ rw,
                              const float* __restrict__ rb) {
    __shared__ __align__(16) float xs[Hd];
    __shared__ float logits[Ee];
    const int t   = blockIdx.x;
    const int tid = threadIdx.x;
    const float* xt = x + (size_t)t * Hd;

    for (int i = tid; i < Hd / 4; i += 128)
        ((float4*)xs)[i] = ((const float4*)xt)[i];
    __syncthreads();

    const int lane = tid & 31, wid = tid >> 5;
    for (int ei = 0; ei < 8; ei++) {
        int e = wid * 8 + ei;
        const float4* wr = (const float4*)(rw + (size_t)e * Hd);
        float s = 0.f;
        for (int i = lane; i < Hd / 4; i += 32) {
            float4 a = ((const float4*)xs)[i];
            float4 b = wr[i];
            s += a.x * b.x + a.y * b.y + a.z * b.z + a.w * b.w;
        }
        #pragma unroll
        for (int o = 16; o; o >>= 1) s += __shfl_xor_sync(0xffffffffu, s, o);
        if (lane == 0) logits[e] = s;
    }
    __syncthreads();

    if (tid < Ee) g_combine[t * Ee + tid] = 0.f;
    __syncthreads();

    if (tid == 0) {
        float sc[Ee], sfc[Ee];
        for (int e = 0; e < Ee; e++) {
            float v = 1.f / (1.f + expf(-logits[e]));
            sc[e]  = v;
            sfc[e] = v + rb[e];
        }
        float gs[NGROUP];
        for (int g = 0; g < NGROUP; g++) {
            float m1 = -1e30f, m2 = -1e30f;
            for (int j = 0; j < GSZ; j++) {
                float v = sfc[g * GSZ + j];
                if (v > m1) { m2 = m1; m1 = v; }
                else if (v > m2) m2 = v;
            }
            gs[g] = m1 + m2;
        }
        bool gsel[NGROUP];
        for (int g = 0; g < NGROUP; g++) gsel[g] = false;
        for (int k = 0; k < TKG; k++) {
            int bi = -1; float bv = -1e30f;
            for (int g = 0; g < NGROUP; g++)
                if (!gsel[g] && gs[g] > bv) { bv = gs[g]; bi = g; }
            gsel[bi] = true;
        }
        float masked[Ee];
        for (int e = 0; e < Ee; e++) masked[e] = gsel[e / GSZ] ? sfc[e] : 0.0f;

        int   idx[TOPK]; float tw[TOPK]; float tsum = 0.f;
        for (int k = 0; k < TOPK; k++) {
            int bi = 0; float bv = -1e30f;
            for (int e = 0; e < Ee; e++)
                if (masked[e] > bv) { bv = masked[e]; bi = e; }
            masked[bi] = -1e30f;
            idx[k] = bi; tw[k] = sc[bi]; tsum += sc[bi];
        }
        float inv = SCALEF / (tsum + 1e-20f);
        for (int k = 0; k < TOPK; k++) {
            int e = idx[k];
            g_combine[t * Ee + e] = tw[k] * inv;
            int slot = atomicAdd(&g_cnt[e], 1);
            g_tok[e * Tt + slot] = t;
        }
    }
}

// ------- tf32 warp-mma GEMM: 128x128x32 block, 4 warps (64x64 each), 2 CTAs/SM -------
#define BM 128
#define BN 128
#define BK 32
#define STAGES 3
#define NTHR 128
#define ASTR 36          // floats per A row (conflict-free frag reads)
#define BSTR 136         // floats per B row (conflict-free frag reads)
#define ASTAGE (BM * ASTR)   // 4608 floats
#define BSTAGE (BK * BSTR)   // 4352 floats
#define SMEM_BYTES (STAGES * (ASTAGE + BSTAGE) * 4)   // 107520

__device__ __forceinline__ uint32_t f2tf32(float f) {
    uint32_t r;
    asm("cvt.rna.tf32.f32 %0, %1;" : "=r"(r) : "f"(f));
    return r;
}

__device__ __forceinline__ void mma_tf32(float (&c)[4], const uint32_t (&a)[4],
                                         const uint32_t (&b)[2]) {
    asm volatile(
        "mma.sync.aligned.m16n8k8.row.col.f32.tf32.tf32.f32 "
        "{%0,%1,%2,%3}, {%4,%5,%6,%7}, {%8,%9}, {%0,%1,%2,%3};\n"
        : "+f"(c[0]), "+f"(c[1]), "+f"(c[2]), "+f"(c[3])
        : "r"(a[0]), "r"(a[1]), "r"(a[2]), "r"(a[3]), "r"(b[0]), "r"(b[1]));
}

__device__ __forceinline__ void cp16(uint32_t dst, const void* src, bool valid) {
    int sz = valid ? 16 : 0;
    asm volatile("cp.async.cg.shared.global [%0], [%1], 16, %2;\n"
                 :: "r"(dst), "l"(src), "r"(sz));
}
__device__ __forceinline__ void cp_commit() {
    asm volatile("cp.async.commit_group;\n");
}
__device__ __forceinline__ void cp_wait() {
    asm volatile("cp.async.wait_group %0;\n" :: "n"(STAGES - 2));
}

__device__ __forceinline__ void red2(float* p, float v0, float v1) {
    asm volatile("red.global.add.v2.f32 [%0], {%1,%2};\n" :: "l"(p), "f"(v0), "f"(v1));
}

// MODE 0: shared up   (A = x,        B = shared_up,   C = g_s1,  relu2)
// MODE 1: shared down (A = g_s1,     B = shared_down, C = out,   plain store)
// MODE 2: moe up      (A = x gather, B = w_up[e],     C = g_act, relu2*combine)
// MODE 3: moe down    (A = g_act,    B = w_down[e],   C = out,   atomic scatter)
template <int MODE>
__global__ __launch_bounds__(NTHR)
void gemm_kernel(const float* __restrict__ Aglob, const float* __restrict__ Bglob,
                 float* __restrict__ Cglob) {
    extern __shared__ float smem[];
    float* As = smem;
    float* Bs = smem + STAGES * ASTAGE;

    constexpr int Kk = (MODE == 1) ? DS : ((MODE == 3) ? DF : Hd);
    constexpr int Nn = (MODE == 0) ? DS : ((MODE == 2) ? DF : Hd);

    const int tid = threadIdx.x;
    const int e  = (MODE >= 2) ? blockIdx.z : 0;
    const int m0 = blockIdx.y * BM;
    const int n0 = blockIdx.x * BN;

    int ne = Tt, off_e = 0;
    const float* Ap = Aglob;
    const float* Bp = Bglob;
    if (MODE == 1) Ap = g_s1;
    if (MODE == 3) Ap = g_act;
    if (MODE >= 2) {
        ne = g_cnt[e];
        if (m0 >= ne) return;
        off_e = g_off[e];
        Bp = Bglob + (size_t)e * Kk * Nn;
    }

    // ---- loader mapping (cp.async, 16B chunks, 128 threads) ----
    // A: 1024 chunks -> 8/thread; row = (tid>>3) + 16*i, col4 = (tid&7)*4
    const int ar0 = tid >> 3;           // 0..15
    const int ac4 = (tid & 7) * 4;
    const float* aSrc[8];
    #pragma unroll
    for (int i = 0; i < 8; i++) {
        int r = m0 + ar0 + i * 16;
        int grow;
        if (MODE == 2)      grow = (r < ne) ? g_tok[e * Tt + r] : -1;
        else if (MODE == 3) grow = (r < ne) ? (off_e + r) : -1;
        else                grow = r;
        aSrc[i] = (grow >= 0) ? (Ap + (size_t)grow * Kk + ac4) : nullptr;
    }
    uint32_t aDst = (uint32_t)__cvta_generic_to_shared(As) + (ar0 * ASTR + ac4) * 4;

    // B: 1024 chunks -> 8/thread; k = (tid>>5) + 4*i, col4 = (tid&31)*4
    const int br0 = tid >> 5;           // 0..3
    const int bc4 = (tid & 31) * 4;
    const float* bSrc = Bp + (size_t)br0 * Nn + n0 + bc4;
    uint32_t bDst = (uint32_t)__cvta_generic_to_shared(Bs) + (br0 * BSTR + bc4) * 4;

    auto issue = [&](int k0, int st) {
        uint32_t ad = aDst + st * (ASTAGE * 4);
        #pragma unroll
        for (int i = 0; i < 8; i++)
            cp16(ad + i * (16 * ASTR * 4),
                 aSrc[i] ? (aSrc[i] + k0) : Ap, aSrc[i] != nullptr);
        uint32_t bd = bDst + st * (BSTAGE * 4);
        const float* bp = bSrc + (size_t)k0 * Nn;
        #pragma unroll
        for (int i = 0; i < 8; i++)
            cp16(bd + i * (4 * BSTR * 4), bp + (size_t)i * 4 * Nn, true);
        cp_commit();
    };

    // ---- warp tiling: 2(m) x 2(n) warps, 64x64 per warp ----
    const int lane = tid & 31, wid = tid >> 5;
    const int qr = lane >> 2, qc = lane & 3;
    const int mb = (wid & 1) * 64;
    const int nb = (wid >> 1) * 64;

    float acc[4][8][4];
    #pragma unroll
    for (int mt = 0; mt < 4; mt++)
        #pragma unroll
        for (int nt = 0; nt < 8; nt++)
            #pragma unroll
            for (int j = 0; j < 4; j++) acc[mt][nt][j] = 0.f;

    const int nk = Kk / BK;

    #pragma unroll
    for (int s = 0; s < STAGES - 1; s++) issue(s * BK, s);

    for (int kb = 0; kb < nk; kb++) {
        cp_wait();
        __syncthreads();   // single barrier per K-tile (3-stage rotation makes the
                           // write-after-read hazard impossible before the next barrier)

        if (kb + STAGES - 1 < nk) issue((kb + STAGES - 1) * BK, (kb + STAGES - 1) % STAGES);
        else                      cp_commit();   // keep group counts aligned

        const uint32_t* Au = (const uint32_t*)(As + (kb % STAGES) * ASTAGE);
        const uint32_t* Bu = (const uint32_t*)(Bs + (kb % STAGES) * BSTAGE);

        #pragma unroll
        for (int ks = 0; ks < BK; ks += 8) {
            uint32_t a[4][4], b[8][2];
            #pragma unroll
            for (int mt = 0; mt < 4; mt++) {
                int r  = mb + mt * 16 + qr;
                int kc = ks + qc;
                a[mt][0] = f2tf32(__uint_as_float(Au[r * ASTR + kc]));
                a[mt][1] = f2tf32(__uint_as_float(Au[(r + 8) * ASTR + kc]));
                a[mt][2] = f2tf32(__uint_as_float(Au[r * ASTR + kc + 4]));
                a[mt][3] = f2tf32(__uint_as_float(Au[(r + 8) * ASTR + kc + 4]));
            }
            #pragma unroll
            for (int nt = 0; nt < 8; nt++) {
                int n = nb + nt * 8 + qr;
                b[nt][0] = f2tf32(__uint_as_float(Bu[(ks + qc) * BSTR + n]));
                b[nt][1] = f2tf32(__uint_as_float(Bu[(ks + qc + 4) * BSTR + n]));
            }
            #pragma unroll
            for (int mt = 0; mt < 4; mt++)
                #pragma unroll
                for (int nt = 0; nt < 8; nt++)
                    mma_tf32(acc[mt][nt], a[mt], b[nt]);
        }
    }

    // -------- epilogue --------
    #pragma unroll
    for (int mt = 0; mt < 4; mt++) {
        int rl0 = mb + mt * 16 + qr;
        int rl1 = rl0 + 8;
        if (MODE == 0 || MODE == 1) {
            int r0 = m0 + rl0, r1 = m0 + rl1;
            float* Cb = (MODE == 0) ? g_s1 : Cglob;
            #pragma unroll
            for (int nt = 0; nt < 8; nt++) {
                int c = n0 + nb + nt * 8 + qc * 2;
                float v0 = acc[mt][nt][0], v1 = acc[mt][nt][1];
                float v2 = acc[mt][nt][2], v3 = acc[mt][nt][3];
                if (MODE == 0) {
                    v0 = fmaxf(v0, 0.f); v0 *= v0;
                    v1 = fmaxf(v1, 0.f); v1 *= v1;
                    v2 = fmaxf(v2, 0.f); v2 *= v2;
                    v3 = fmaxf(v3, 0.f); v3 *= v3;
                }
                *(float2*)&Cb[(size_t)r0 * Nn + c] = make_float2(v0, v1);
                *(float2*)&Cb[(size_t)r1 * Nn + c] = make_float2(v2, v3);
            }
        } else if (MODE == 2) {
            bool va = (m0 + rl0) < ne, vb = (m0 + rl1) < ne;
            int tk0 = va ? g_tok[e * Tt + m0 + rl0] : 0;
            int tk1 = vb ? g_tok[e * Tt + m0 + rl1] : 0;
            float w0 = va ? g_combine[tk0 * Ee + e] : 0.f;
            float w1 = vb ? g_combine[tk1 * Ee + e] : 0.f;
            size_t cr0 = (size_t)(off_e + m0 + rl0) * DF;
            size_t cr1 = (size_t)(off_e + m0 + rl1) * DF;
            #pragma unroll
            for (int nt = 0; nt < 8; nt++) {
                int c = n0 + nb + nt * 8 + qc * 2;
                float v0 = fmaxf(acc[mt][nt][0], 0.f); v0 = v0 * v0 * w0;
                float v1 = fmaxf(acc[mt][nt][1], 0.f); v1 = v1 * v1 * w0;
                float v2 = fmaxf(acc[mt][nt][2], 0.f); v2 = v2 * v2 * w1;
                float v3 = fmaxf(acc[mt][nt][3], 0.f); v3 = v3 * v3 * w1;
                if (va) *(float2*)&g_act[cr0 + c] = make_float2(v0, v1);
                if (vb) *(float2*)&g_act[cr1 + c] = make_float2(v2, v3);
            }
        } else {  // MODE 3: vector atomic scatter into out
            bool va = (m0 + rl0) < ne, vb = (m0 + rl1) < ne;
            int tk0 = va ? g_tok[e * Tt + m0 + rl0] : 0;
            int tk1 = vb ? g_tok[e * Tt + m0 + rl1] : 0;
            #pragma unroll
            for (int nt = 0; nt < 8; nt++) {
                int c = n0 + nb + nt * 8 + qc * 2;
                if (va) red2(&Cglob[(size_t)tk0 * Hd + c], acc[mt][nt][0], acc[mt][nt][1]);
                if (vb) red2(&Cglob[(size_t)tk1 * Hd + c], acc[mt][nt][2], acc[mt][nt][3]);
            }
        }
    }
}

// ---------------- launch ----------------
extern "C" void kernel_launch(void* const* d_in, const int* in_sizes, int n_in,
                              void* d_out, int out_size) {
    const float* x     = (const float*)d_in[0];
    const float* rw    = (const float*)d_in[1];
    const float* rb    = (const float*)d_in[2];
    const float* w_up  = (const float*)d_in[3];
    const float* w_dn  = (const float*)d_in[4];
    const float* s_up  = (const float*)d_in[5];
    const float* s_dn  = (const float*)d_in[6];
    float* out = (float*)d_out;

    cudaFuncSetAttribute(gemm_kernel<0>, cudaFuncAttributeMaxDynamicSharedMemorySize, SMEM_BYTES);
    cudaFuncSetAttribute(gemm_kernel<1>, cudaFuncAttributeMaxDynamicSharedMemorySize, SMEM_BYTES);
    cudaFuncSetAttribute(gemm_kernel<2>, cudaFuncAttributeMaxDynamicSharedMemorySize, SMEM_BYTES);
    cudaFuncSetAttribute(gemm_kernel<3>, cudaFuncAttributeMaxDynamicSharedMemorySize, SMEM_BYTES);

    zero_cnt_kernel<<<1, 32>>>();
    router_kernel<<<Tt, 128>>>(x, rw, rb);
    offs_kernel<<<1, 32>>>();

    // routed up: per-expert gathered GEMM -> g_act
    gemm_kernel<2><<<dim3(DF / BN, Tt / BM, Ee), NTHR, SMEM_BYTES>>>(x, w_up, nullptr);

    // shared expert
    gemm_kernel<0><<<dim3(DS / BN, Tt / BM, 1), NTHR, SMEM_BYTES>>>(x, s_up, nullptr);
    gemm_kernel<1><<<dim3(Hd / BN, Tt / BM, 1), NTHR, SMEM_BYTES>>>(nullptr, s_dn, out);

    // routed down: atomic scatter onto out (after shared wrote it)
    gemm_kernel<3><<<dim3(Hd / BN, Tt / BM, Ee), NTHR, SMEM_BYTES>>>(nullptr, w_dn, out);
}

// round 11
// speedup vs baseline: 1.0930x; 1.0030x over previous
#include <cuda_runtime.h>
#include <cstdint>

#define Tt   2048
#define Hd   2048
#define Ee   32
#define DF   1024
#define DS   4096
#define TOPK 6
#define NGROUP 8
#define GSZ  4
#define TKG  4
#define SCALEF 2.5f

// ---------------- static device scratch (no allocations allowed) ----------------
__device__ float g_combine[Tt * Ee];
__device__ int   g_cnt[Ee];
__device__ int   g_off[Ee];
__device__ int   g_tok[Ee * Tt];
__device__ float g_act[(size_t)Tt * TOPK * DF];
__device__ float g_s1[(size_t)Tt * DS];

// ---------------- small kernels ----------------
__global__ void zero_cnt_kernel() {
    if (threadIdx.x < Ee) g_cnt[threadIdx.x] = 0;
}
__global__ void offs_kernel() {
    if (threadIdx.x == 0) {
        int r = 0;
        for (int e = 0; e < Ee; e++) { g_off[e] = r; r += g_cnt[e]; }
    }
}

// ---------------- router: one block (128 thr) per token ----------------
__global__ void router_kernel(const float* __restrict__ x,
                              const float* __restrict__ rw,
                              const float* __restrict__ rb) {
    __shared__ __align__(16) float xs[Hd];
    __shared__ float logits[Ee];
    const int t   = blockIdx.x;
    const int tid = threadIdx.x;
    const float* xt = x + (size_t)t * Hd;

    for (int i = tid; i < Hd / 4; i += 128)
        ((float4*)xs)[i] = ((const float4*)xt)[i];
    __syncthreads();

    const int lane = tid & 31, wid = tid >> 5;
    for (int ei = 0; ei < 8; ei++) {
        int e = wid * 8 + ei;
        const float4* wr = (const float4*)(rw + (size_t)e * Hd);
        float s = 0.f;
        for (int i = lane; i < Hd / 4; i += 32) {
            float4 a = ((const float4*)xs)[i];
            float4 b = wr[i];
            s += a.x * b.x + a.y * b.y + a.z * b.z + a.w * b.w;
        }
        #pragma unroll
        for (int o = 16; o; o >>= 1) s += __shfl_xor_sync(0xffffffffu, s, o);
        if (lane == 0) logits[e] = s;
    }
    __syncthreads();

    if (tid < Ee) g_combine[t * Ee + tid] = 0.f;
    __syncthreads();

    if (tid == 0) {
        float sc[Ee], sfc[Ee];
        for (int e = 0; e < Ee; e++) {
            float v = 1.f / (1.f + expf(-logits[e]));
            sc[e]  = v;
            sfc[e] = v + rb[e];
        }
        float gs[NGROUP];
        for (int g = 0; g < NGROUP; g++) {
            float m1 = -1e30f, m2 = -1e30f;
            for (int j = 0; j < GSZ; j++) {
                float v = sfc[g * GSZ + j];
                if (v > m1) { m2 = m1; m1 = v; }
                else if (v > m2) m2 = v;
            }
            gs[g] = m1 + m2;
        }
        bool gsel[NGROUP];
        for (int g = 0; g < NGROUP; g++) gsel[g] = false;
        for (int k = 0; k < TKG; k++) {
            int bi = -1; float bv = -1e30f;
            for (int g = 0; g < NGROUP; g++)
                if (!gsel[g] && gs[g] > bv) { bv = gs[g]; bi = g; }
            gsel[bi] = true;
        }
        float masked[Ee];
        for (int e = 0; e < Ee; e++) masked[e] = gsel[e / GSZ] ? sfc[e] : 0.0f;

        int   idx[TOPK]; float tw[TOPK]; float tsum = 0.f;
        for (int k = 0; k < TOPK; k++) {
            int bi = 0; float bv = -1e30f;
            for (int e = 0; e < Ee; e++)
                if (masked[e] > bv) { bv = masked[e]; bi = e; }
            masked[bi] = -1e30f;
            idx[k] = bi; tw[k] = sc[bi]; tsum += sc[bi];
        }
        float inv = SCALEF / (tsum + 1e-20f);
        for (int k = 0; k < TOPK; k++) {
            int e = idx[k];
            g_combine[t * Ee + e] = tw[k] * inv;
            int slot = atomicAdd(&g_cnt[e], 1);
            g_tok[e * Tt + slot] = t;
        }
    }
}

// ------- tf32 warp-mma GEMM: 128x128x32 block, 4 warps (64x64), reg-double-buffered frags -------
#define BM 128
#define BN 128
#define BK 32
#define STAGES 3
#define NTHR 128
#define ASTR 36          // floats per A row (conflict-free frag reads)
#define BSTR 136         // floats per B row (conflict-free frag reads)
#define ASTAGE (BM * ASTR)   // 4608 floats
#define BSTAGE (BK * BSTR)   // 4352 floats
#define SMEM_BYTES (STAGES * (ASTAGE + BSTAGE) * 4)   // 107520

__device__ __forceinline__ uint32_t f2tf32(float f) {
    uint32_t r;
    asm("cvt.rna.tf32.f32 %0, %1;" : "=r"(r) : "f"(f));
    return r;
}

__device__ __forceinline__ void mma_tf32(float (&c)[4], const uint32_t (&a)[4],
                                         const uint32_t (&b)[2]) {
    asm volatile(
        "mma.sync.aligned.m16n8k8.row.col.f32.tf32.tf32.f32 "
        "{%0,%1,%2,%3}, {%4,%5,%6,%7}, {%8,%9}, {%0,%1,%2,%3};\n"
        : "+f"(c[0]), "+f"(c[1]), "+f"(c[2]), "+f"(c[3])
        : "r"(a[0]), "r"(a[1]), "r"(a[2]), "r"(a[3]), "r"(b[0]), "r"(b[1]));
}

__device__ __forceinline__ void cp16(uint32_t dst, const void* src, bool valid) {
    int sz = valid ? 16 : 0;
    asm volatile("cp.async.cg.shared.global [%0], [%1], 16, %2;\n"
                 :: "r"(dst), "l"(src), "r"(sz));
}
__device__ __forceinline__ void cp_commit() {
    asm volatile("cp.async.commit_group;\n");
}
__device__ __forceinline__ void cp_wait() {
    asm volatile("cp.async.wait_group %0;\n" :: "n"(STAGES - 2));
}

__device__ __forceinline__ void red2(float* p, float v0, float v1) {
    asm volatile("red.global.add.v2.f32 [%0], {%1,%2};\n" :: "l"(p), "f"(v0), "f"(v1));
}

// MODE 0: shared up   (A = x,        B = shared_up,   C = g_s1,  relu2)
// MODE 1: shared down (A = g_s1,     B = shared_down, C = out,   plain store)
// MODE 2: moe up      (A = x gather, B = w_up[e],     C = g_act, relu2*combine)
// MODE 3: moe down    (A = g_act,    B = w_down[e],   C = out,   atomic scatter)
template <int MODE>
__global__ __launch_bounds__(NTHR, 2)
void gemm_kernel(const float* __restrict__ Aglob, const float* __restrict__ Bglob,
                 float* __restrict__ Cglob) {
    extern __shared__ float smem[];
    float* As = smem;
    float* Bs = smem + STAGES * ASTAGE;

    constexpr int Kk = (MODE == 1) ? DS : ((MODE == 3) ? DF : Hd);
    constexpr int Nn = (MODE == 0) ? DS : ((MODE == 2) ? DF : Hd);

    const int tid = threadIdx.x;
    const int e  = (MODE >= 2) ? blockIdx.z : 0;
    const int m0 = blockIdx.y * BM;
    const int n0 = blockIdx.x * BN;

    int ne = Tt, off_e = 0;
    const float* Ap = Aglob;
    const float* Bp = Bglob;
    if (MODE == 1) Ap = g_s1;
    if (MODE == 3) Ap = g_act;
    if (MODE >= 2) {
        ne = g_cnt[e];
        if (m0 >= ne) return;
        off_e = g_off[e];
        Bp = Bglob + (size_t)e * Kk * Nn;
    }

    // ---- loader mapping (cp.async, 16B chunks, 128 threads) ----
    const int ar0 = tid >> 3;           // 0..15
    const int ac4 = (tid & 7) * 4;
    const float* aSrc[8];
    #pragma unroll
    for (int i = 0; i < 8; i++) {
        int r = m0 + ar0 + i * 16;
        int grow;
        if (MODE == 2)      grow = (r < ne) ? g_tok[e * Tt + r] : -1;
        else if (MODE == 3) grow = (r < ne) ? (off_e + r) : -1;
        else                grow = r;
        aSrc[i] = (grow >= 0) ? (Ap + (size_t)grow * Kk + ac4) : nullptr;
    }
    uint32_t aDst = (uint32_t)__cvta_generic_to_shared(As) + (ar0 * ASTR + ac4) * 4;

    const int br0 = tid >> 5;           // 0..3
    const int bc4 = (tid & 31) * 4;
    const float* bSrc = Bp + (size_t)br0 * Nn + n0 + bc4;
    uint32_t bDst = (uint32_t)__cvta_generic_to_shared(Bs) + (br0 * BSTR + bc4) * 4;

    auto issue = [&](int k0, int st) {
        uint32_t ad = aDst + st * (ASTAGE * 4);
        #pragma unroll
        for (int i = 0; i < 8; i++)
            cp16(ad + i * (16 * ASTR * 4),
                 aSrc[i] ? (aSrc[i] + k0) : Ap, aSrc[i] != nullptr);
        uint32_t bd = bDst + st * (BSTAGE * 4);
        const float* bp = bSrc + (size_t)k0 * Nn;
        #pragma unroll
        for (int i = 0; i < 8; i++)
            cp16(bd + i * (4 * BSTR * 4), bp + (size_t)i * 4 * Nn, true);
        cp_commit();
    };

    // ---- warp tiling: 2(m) x 2(n) warps, 64x64 per warp ----
    const int lane = tid & 31, wid = tid >> 5;
    const int qr = lane >> 2, qc = lane & 3;
    const int mb = (wid & 1) * 64;
    const int nb = (wid >> 1) * 64;

    float acc[4][8][4];
    #pragma unroll
    for (int mt = 0; mt < 4; mt++)
        #pragma unroll
        for (int nt = 0; nt < 8; nt++)
            #pragma unroll
            for (int j = 0; j < 4; j++) acc[mt][nt][j] = 0.f;

    // double-buffered fragment registers
    uint32_t afr[2][4][4], bfr[2][8][2];

    const int nk = Kk / BK;

    #pragma unroll
    for (int s = 0; s < STAGES - 1; s++) issue(s * BK, s);

    for (int kb = 0; kb < nk; kb++) {
        cp_wait();
        __syncthreads();   // single barrier per K-tile (3-stage rotation)

        if (kb + STAGES - 1 < nk) issue((kb + STAGES - 1) * BK, (kb + STAGES - 1) % STAGES);
        else                      cp_commit();   // keep group counts aligned

        const uint32_t* Au = (const uint32_t*)(As + (kb % STAGES) * ASTAGE);
        const uint32_t* Bu = (const uint32_t*)(Bs + (kb % STAGES) * BSTAGE);

        // prefetch fragments for ks=0 into buffer 0
        #pragma unroll
        for (int mt = 0; mt < 4; mt++) {
            int r = mb + mt * 16 + qr;
            afr[0][mt][0] = f2tf32(__uint_as_float(Au[r * ASTR + qc]));
            afr[0][mt][1] = f2tf32(__uint_as_float(Au[(r + 8) * ASTR + qc]));
            afr[0][mt][2] = f2tf32(__uint_as_float(Au[r * ASTR + qc + 4]));
            afr[0][mt][3] = f2tf32(__uint_as_float(Au[(r + 8) * ASTR + qc + 4]));
        }
        #pragma unroll
        for (int nt = 0; nt < 8; nt++) {
            int n = nb + nt * 8 + qr;
            bfr[0][nt][0] = f2tf32(__uint_as_float(Bu[qc * BSTR + n]));
            bfr[0][nt][1] = f2tf32(__uint_as_float(Bu[(qc + 4) * BSTR + n]));
        }

        #pragma unroll
        for (int kq = 0; kq < 4; kq++) {
            const int cur = kq & 1;
            // prefetch next k-step's fragments BEFORE issuing this step's MMAs;
            // the 32-MMA burst below hides the LDS(29cyc)+cvt chain entirely.
            if (kq < 3) {
                const int nxt = cur ^ 1;
                const int ks = (kq + 1) * 8;
                #pragma unroll
                for (int mt = 0; mt < 4; mt++) {
                    int r  = mb + mt * 16 + qr;
                    int kc = ks + qc;
                    afr[nxt][mt][0] = f2tf32(__uint_as_float(Au[r * ASTR + kc]));
                    afr[nxt][mt][1] = f2tf32(__uint_as_float(Au[(r + 8) * ASTR + kc]));
                    afr[nxt][mt][2] = f2tf32(__uint_as_float(Au[r * ASTR + kc + 4]));
                    afr[nxt][mt][3] = f2tf32(__uint_as_float(Au[(r + 8) * ASTR + kc + 4]));
                }
                #pragma unroll
                for (int nt = 0; nt < 8; nt++) {
                    int n = nb + nt * 8 + qr;
                    bfr[nxt][nt][0] = f2tf32(__uint_as_float(Bu[(ks + qc) * BSTR + n]));
                    bfr[nxt][nt][1] = f2tf32(__uint_as_float(Bu[(ks + qc + 4) * BSTR + n]));
                }
            }
            #pragma unroll
            for (int mt = 0; mt < 4; mt++)
                #pragma unroll
                for (int nt = 0; nt < 8; nt++)
                    mma_tf32(acc[mt][nt], afr[cur][mt], bfr[cur][nt]);
        }
    }

    // -------- epilogue --------
    #pragma unroll
    for (int mt = 0; mt < 4; mt++) {
        int rl0 = mb + mt * 16 + qr;
        int rl1 = rl0 + 8;
        if (MODE == 0 || MODE == 1) {
            int r0 = m0 + rl0, r1 = m0 + rl1;
            float* Cb = (MODE == 0) ? g_s1 : Cglob;
            #pragma unroll
            for (int nt = 0; nt < 8; nt++) {
                int c = n0 + nb + nt * 8 + qc * 2;
                float v0 = acc[mt][nt][0], v1 = acc[mt][nt][1];
                float v2 = acc[mt][nt][2], v3 = acc[mt][nt][3];
                if (MODE == 0) {
                    v0 = fmaxf(v0, 0.f); v0 *= v0;
                    v1 = fmaxf(v1, 0.f); v1 *= v1;
                    v2 = fmaxf(v2, 0.f); v2 *= v2;
                    v3 = fmaxf(v3, 0.f); v3 *= v3;
                }
                *(float2*)&Cb[(size_t)r0 * Nn + c] = make_float2(v0, v1);
                *(float2*)&Cb[(size_t)r1 * Nn + c] = make_float2(v2, v3);
            }
        } else if (MODE == 2) {
            bool va = (m0 + rl0) < ne, vb = (m0 + rl1) < ne;
            int tk0 = va ? g_tok[e * Tt + m0 + rl0] : 0;
            int tk1 = vb ? g_tok[e * Tt + m0 + rl1] : 0;
            float w0 = va ? g_combine[tk0 * Ee + e] : 0.f;
            float w1 = vb ? g_combine[tk1 * Ee + e] : 0.f;
            size_t cr0 = (size_t)(off_e + m0 + rl0) * DF;
            size_t cr1 = (size_t)(off_e + m0 + rl1) * DF;
            #pragma unroll
            for (int nt = 0; nt < 8; nt++) {
                int c = n0 + nb + nt * 8 + qc * 2;
                float v0 = fmaxf(acc[mt][nt][0], 0.f); v0 = v0 * v0 * w0;
                float v1 = fmaxf(acc[mt][nt][1], 0.f); v1 = v1 * v1 * w0;
                float v2 = fmaxf(acc[mt][nt][2], 0.f); v2 = v2 * v2 * w1;
                float v3 = fmaxf(acc[mt][nt][3], 0.f); v3 = v3 * v3 * w1;
                if (va) *(float2*)&g_act[cr0 + c] = make_float2(v0, v1);
                if (vb) *(float2*)&g_act[cr1 + c] = make_float2(v2, v3);
            }
        } else {  // MODE 3: vector atomic scatter into out
            bool va = (m0 + rl0) < ne, vb = (m0 + rl1) < ne;
            int tk0 = va ? g_tok[e * Tt + m0 + rl0] : 0;
            int tk1 = vb ? g_tok[e * Tt + m0 + rl1] : 0;
            #pragma unroll
            for (int nt = 0; nt < 8; nt++) {
                int c = n0 + nb + nt * 8 + qc * 2;
                if (va) red2(&Cglob[(size_t)tk0 * Hd + c], acc[mt][nt][0], acc[mt][nt][1]);
                if (vb) red2(&Cglob[(size_t)tk1 * Hd + c], acc[mt][nt][2], acc[mt][nt][3]);
            }
        }
    }
}

// ---------------- launch ----------------
extern "C" void kernel_launch(void* const* d_in, const int* in_sizes, int n_in,
                              void* d_out, int out_size) {
    const float* x     = (const float*)d_in[0];
    const float* rw    = (const float*)d_in[1];
    const float* rb    = (const float*)d_in[2];
    const float* w_up  = (const float*)d_in[3];
    const float* w_dn  = (const float*)d_in[4];
    const float* s_up  = (const float*)d_in[5];
    const float* s_dn  = (const float*)d_in[6];
    float* out = (float*)d_out;

    cudaFuncSetAttribute(gemm_kernel<0>, cudaFuncAttributeMaxDynamicSharedMemorySize, SMEM_BYTES);
    cudaFuncSetAttribute(gemm_kernel<1>, cudaFuncAttributeMaxDynamicSharedMemorySize, SMEM_BYTES);
    cudaFuncSetAttribute(gemm_kernel<2>, cudaFuncAttributeMaxDynamicSharedMemorySize, SMEM_BYTES);
    cudaFuncSetAttribute(gemm_kernel<3>, cudaFuncAttributeMaxDynamicSharedMemorySize, SMEM_BYTES);

    zero_cnt_kernel<<<1, 32>>>();
    router_kernel<<<Tt, 128>>>(x, rw, rb);
    offs_kernel<<<1, 32>>>();

    // routed up: per-expert gathered GEMM -> g_act
    gemm_kernel<2><<<dim3(DF / BN, Tt / BM, Ee), NTHR, SMEM_BYTES>>>(x, w_up, nullptr);

    // shared expert
    gemm_kernel<0><<<dim3(DS / BN, Tt / BM, 1), NTHR, SMEM_BYTES>>>(x, s_up, nullptr);
    gemm_kernel<1><<<dim3(Hd / BN, Tt / BM, 1), NTHR, SMEM_BYTES>>>(nullptr, s_dn, out);

    // routed down: atomic scatter onto out (after shared wrote it)
    gemm_kernel<3><<<dim3(Hd / BN, Tt / BM, Ee), NTHR, SMEM_BYTES>>>(nullptr, w_dn, out);
}

// round 12
// speedup vs baseline: 1.7468x; 1.5983x over previous
#include <cuda_runtime.h>
#include <cuda_fp16.h>
#include <cstdint>

#define Tt   2048
#define Hd   2048
#define Ee   32
#define DF   1024
#define DS   4096
#define TOPK 6
#define NGROUP 8
#define GSZ  4
#define TKG  4
#define SCALEF 2.5f

// ---------------- static device scratch (no allocations allowed) ----------------
__device__ float g_combine[Tt * Ee];
__device__ int   g_cnt[Ee];
__device__ int   g_off[Ee];
__device__ int   g_tok[Ee * Tt];

__device__ __align__(16) __half g_xh  [(size_t)Tt * Hd];        // x in fp16 (k-major)
__device__ __align__(16) __half g_wupt[(size_t)Ee * DF * Hd];   // w_up^T  [E][DF][Hd]
__device__ __align__(16) __half g_wdnt[(size_t)Ee * Hd * DF];   // w_down^T[E][Hd][DF]
__device__ __align__(16) __half g_supt[(size_t)DS * Hd];        // shared_up^T  [DS][Hd]
__device__ __align__(16) __half g_sdnt[(size_t)Hd * DS];        // shared_down^T[Hd][DS]
__device__ __align__(16) __half g_s1h [(size_t)Tt * DS];        // shared intermediate fp16
__device__ __align__(16) __half g_acth[(size_t)Tt * TOPK * DF]; // routed act fp16

// ---------------- small kernels ----------------
__global__ void zero_cnt_kernel() {
    if (threadIdx.x < Ee) g_cnt[threadIdx.x] = 0;
}
__global__ void offs_kernel() {
    if (threadIdx.x == 0) {
        int r = 0;
        for (int e = 0; e < Ee; e++) { g_off[e] = r; r += g_cnt[e]; }
    }
}

// x fp32 -> fp16 (layout preserved, k-major)
__global__ void cvt_x_kernel(const float* __restrict__ x) {
    int i = blockIdx.x * 256 + threadIdx.x;          // one float4 per thread
    float4 v = ((const float4*)x)[i];
    __half2 h0 = __floats2half2_rn(v.x, v.y);
    __half2 h1 = __floats2half2_rn(v.z, v.w);
    uint2 u;
    u.x = *(uint32_t*)&h0; u.y = *(uint32_t*)&h1;
    ((uint2*)g_xh)[i] = u;
}

// W fp32 [K][N] (batched) -> Wt fp16 [N][K]
__global__ void transp_kernel(const float* __restrict__ W, __half* __restrict__ Wt,
                              int K, int N) {
    __shared__ float tile[32][33];
    const int b = blockIdx.z;
    const float* Wb = W + (size_t)b * K * N;
    __half* Wtb = Wt + (size_t)b * K * N;
    const int k0 = blockIdx.y * 32, n0 = blockIdx.x * 32;
    const int tx = threadIdx.x, ty = threadIdx.y;    // (32, 8)
    #pragma unroll
    for (int j = 0; j < 32; j += 8)
        tile[ty + j][tx] = Wb[(size_t)(k0 + ty + j) * N + n0 + tx];
    __syncthreads();
    #pragma unroll
    for (int j = 0; j < 32; j += 8)
        Wtb[(size_t)(n0 + ty + j) * K + k0 + tx] = __float2half_rn(tile[tx][ty + j]);
}

// ---------------- router: one block (128 thr) per token (fp32, unchanged) ----------------
__global__ void router_kernel(const float* __restrict__ x,
                              const float* __restrict__ rw,
                              const float* __restrict__ rb) {
    __shared__ __align__(16) float xs[Hd];
    __shared__ float logits[Ee];
    const int t   = blockIdx.x;
    const int tid = threadIdx.x;
    const float* xt = x + (size_t)t * Hd;

    for (int i = tid; i < Hd / 4; i += 128)
        ((float4*)xs)[i] = ((const float4*)xt)[i];
    __syncthreads();

    const int lane = tid & 31, wid = tid >> 5;
    for (int ei = 0; ei < 8; ei++) {
        int e = wid * 8 + ei;
        const float4* wr = (const float4*)(rw + (size_t)e * Hd);
        float s = 0.f;
        for (int i = lane; i < Hd / 4; i += 32) {
            float4 a = ((const float4*)xs)[i];
            float4 b = wr[i];
            s += a.x * b.x + a.y * b.y + a.z * b.z + a.w * b.w;
        }
        #pragma unroll
        for (int o = 16; o; o >>= 1) s += __shfl_xor_sync(0xffffffffu, s, o);
        if (lane == 0) logits[e] = s;
    }
    __syncthreads();

    if (tid < Ee) g_combine[t * Ee + tid] = 0.f;
    __syncthreads();

    if (tid == 0) {
        float sc[Ee], sfc[Ee];
        for (int e = 0; e < Ee; e++) {
            float v = 1.f / (1.f + expf(-logits[e]));
            sc[e]  = v;
            sfc[e] = v + rb[e];
        }
        float gs[NGROUP];
        for (int g = 0; g < NGROUP; g++) {
            float m1 = -1e30f, m2 = -1e30f;
            for (int j = 0; j < GSZ; j++) {
                float v = sfc[g * GSZ + j];
                if (v > m1) { m2 = m1; m1 = v; }
                else if (v > m2) m2 = v;
            }
            gs[g] = m1 + m2;
        }
        bool gsel[NGROUP];
        for (int g = 0; g < NGROUP; g++) gsel[g] = false;
        for (int k = 0; k < TKG; k++) {
            int bi = -1; float bv = -1e30f;
            for (int g = 0; g < NGROUP; g++)
                if (!gsel[g] && gs[g] > bv) { bv = gs[g]; bi = g; }
            gsel[bi] = true;
        }
        float masked[Ee];
        for (int e = 0; e < Ee; e++) masked[e] = gsel[e / GSZ] ? sfc[e] : 0.0f;

        int   idx[TOPK]; float tw[TOPK]; float tsum = 0.f;
        for (int k = 0; k < TOPK; k++) {
            int bi = 0; float bv = -1e30f;
            for (int e = 0; e < Ee; e++)
                if (masked[e] > bv) { bv = masked[e]; bi = e; }
            masked[bi] = -1e30f;
            idx[k] = bi; tw[k] = sc[bi]; tsum += sc[bi];
        }
        float inv = SCALEF / (tsum + 1e-20f);
        for (int k = 0; k < TOPK; k++) {
            int e = idx[k];
            g_combine[t * Ee + e] = tw[k] * inv;
            int slot = atomicAdd(&g_cnt[e], 1);
            g_tok[e * Tt + slot] = t;
        }
    }
}

// ------- fp16 warp-mma GEMM: 128x128x32 block, 4 warps (64x64), m16n8k16, cp.async x3 -------
#define BM 128
#define BN 128
#define BK 32           // halves
#define STAGES 3
#define NTHR 128
#define RSTR 20         // u32 per smem row (16 data + 4 pad -> conflict-free frag reads)
#define ASTAGE (BM * RSTR)   // u32
#define BSTAGE (BN * RSTR)
#define SMEM_BYTES (STAGES * (ASTAGE + BSTAGE) * 4)   // 61440

__device__ __forceinline__ void mma_f16(float (&c)[4], const uint32_t (&a)[4],
                                        const uint32_t (&b)[2]) {
    asm volatile(
        "mma.sync.aligned.m16n8k16.row.col.f32.f16.f16.f32 "
        "{%0,%1,%2,%3}, {%4,%5,%6,%7}, {%8,%9}, {%0,%1,%2,%3};\n"
        : "+f"(c[0]), "+f"(c[1]), "+f"(c[2]), "+f"(c[3])
        : "r"(a[0]), "r"(a[1]), "r"(a[2]), "r"(a[3]), "r"(b[0]), "r"(b[1]));
}

__device__ __forceinline__ void cp16(uint32_t dst, const void* src, bool valid) {
    int sz = valid ? 16 : 0;
    asm volatile("cp.async.cg.shared.global [%0], [%1], 16, %2;\n"
                 :: "r"(dst), "l"(src), "r"(sz));
}
__device__ __forceinline__ void cp_commit() {
    asm volatile("cp.async.commit_group;\n");
}
__device__ __forceinline__ void cp_wait() {
    asm volatile("cp.async.wait_group %0;\n" :: "n"(STAGES - 2));
}

__device__ __forceinline__ void red2(float* p, float v0, float v1) {
    asm volatile("red.global.add.v2.f32 [%0], {%1,%2};\n" :: "l"(p), "f"(v0), "f"(v1));
}

// MODE 0: shared up   (A = xh,        B = g_supt,       C = g_s1h fp16, relu2)
// MODE 1: shared down (A = g_s1h,     B = g_sdnt,       C = out fp32)
// MODE 2: moe up      (A = xh gather, B = g_wupt[e],    C = g_acth fp16, relu2*combine)
// MODE 3: moe down    (A = g_acth,    B = g_wdnt[e],    C = out, atomic scatter)
template <int MODE>
__global__ __launch_bounds__(NTHR, 2)
void gemm_kernel(float* __restrict__ Cglob) {
    extern __shared__ uint32_t smem[];
    uint32_t* As = smem;
    uint32_t* Bs = smem + STAGES * ASTAGE;

    constexpr int Kk = (MODE == 1) ? DS : ((MODE == 3) ? DF : Hd);
    constexpr int Nn = (MODE == 0) ? DS : ((MODE == 2) ? DF : Hd);

    const int tid = threadIdx.x;
    const int e  = (MODE >= 2) ? blockIdx.z : 0;
    const int m0 = blockIdx.y * BM;
    const int n0 = blockIdx.x * BN;

    int ne = Tt, off_e = 0;
    const __half* Ah = (MODE == 1) ? g_s1h : ((MODE == 3) ? g_acth : g_xh);
    const __half* Bt;
    if (MODE == 0) Bt = g_supt;
    else if (MODE == 1) Bt = g_sdnt;
    else if (MODE == 2) Bt = g_wupt + (size_t)e * DF * Hd;
    else Bt = g_wdnt + (size_t)e * Hd * DF;

    if (MODE >= 2) {
        ne = g_cnt[e];
        if (m0 >= ne) return;
        off_e = g_off[e];
    }

    // ---- loader mapping (cp.async, 16B = 8 halves per chunk, 128 threads) ----
    const int lr = tid >> 2;            // 0..31
    const int lc = tid & 3;             // chunk within 32-half row
    const __half* aSrc[4];
    #pragma unroll
    for (int i = 0; i < 4; i++) {
        int r = m0 + lr + i * 32;
        int grow;
        if (MODE == 2)      grow = (r < ne) ? g_tok[e * Tt + r] : -1;
        else if (MODE == 3) grow = (r < ne) ? (off_e + r) : -1;
        else                grow = r;
        aSrc[i] = (grow >= 0) ? (Ah + (size_t)grow * Kk + lc * 8) : nullptr;
    }
    const __half* bSrc = Bt + (size_t)(n0 + lr) * Kk + lc * 8;

    const uint32_t aBase = (uint32_t)__cvta_generic_to_shared(As) + ((lr * RSTR + lc * 4) * 4);
    const uint32_t bBase = (uint32_t)__cvta_generic_to_shared(Bs) + ((lr * RSTR + lc * 4) * 4);

    auto issue = [&](int k0, int st) {   // k0 in halves
        uint32_t ad = aBase + st * (ASTAGE * 4);
        #pragma unroll
        for (int i = 0; i < 4; i++)
            cp16(ad + i * (32 * RSTR * 4),
                 aSrc[i] ? (aSrc[i] + k0) : Ah, aSrc[i] != nullptr);
        uint32_t bd = bBase + st * (BSTAGE * 4);
        #pragma unroll
        for (int i = 0; i < 4; i++)
            cp16(bd + i * (32 * RSTR * 4), bSrc + (size_t)i * 32 * Kk + k0, true);
        cp_commit();
    };

    // ---- warp tiling: 2(m) x 2(n) warps, 64x64 per warp ----
    const int lane = tid & 31, wid = tid >> 5;
    const int qr = lane >> 2, qc = lane & 3;
    const int mb = (wid & 1) * 64;
    const int nb = (wid >> 1) * 64;

    float acc[4][8][4];
    #pragma unroll
    for (int mt = 0; mt < 4; mt++)
        #pragma unroll
        for (int nt = 0; nt < 8; nt++)
            #pragma unroll
            for (int j = 0; j < 4; j++) acc[mt][nt][j] = 0.f;

    uint32_t afr[2][4][4], bfr[2][8][2];

    const int nk = Kk / BK;

    #pragma unroll
    for (int s = 0; s < STAGES - 1; s++) issue(s * BK, s);

    for (int kb = 0; kb < nk; kb++) {
        cp_wait();
        __syncthreads();   // single barrier per K-tile (3-stage rotation)

        if (kb + STAGES - 1 < nk) issue((kb + STAGES - 1) * BK, (kb + STAGES - 1) % STAGES);
        else                      cp_commit();   // keep group counts aligned

        const uint32_t* Au = As + (kb % STAGES) * ASTAGE;
        const uint32_t* Bu = Bs + (kb % STAGES) * BSTAGE;

        // k16 step 0 fragments (u32 cols qc / qc+4)
        #pragma unroll
        for (int mt = 0; mt < 4; mt++) {
            int r = mb + mt * 16 + qr;
            afr[0][mt][0] = Au[r * RSTR + qc];
            afr[0][mt][1] = Au[(r + 8) * RSTR + qc];
            afr[0][mt][2] = Au[r * RSTR + qc + 4];
            afr[0][mt][3] = Au[(r + 8) * RSTR + qc + 4];
        }
        #pragma unroll
        for (int nt = 0; nt < 8; nt++) {
            int n = nb + nt * 8 + qr;
            bfr[0][nt][0] = Bu[n * RSTR + qc];
            bfr[0][nt][1] = Bu[n * RSTR + qc + 4];
        }

        #pragma unroll
        for (int s = 0; s < 2; s++) {
            if (s == 0) {   // prefetch k16 step 1 (u32 cols 8+qc / 12+qc)
                #pragma unroll
                for (int mt = 0; mt < 4; mt++) {
                    int r = mb + mt * 16 + qr;
                    afr[1][mt][0] = Au[r * RSTR + 8 + qc];
                    afr[1][mt][1] = Au[(r + 8) * RSTR + 8 + qc];
                    afr[1][mt][2] = Au[r * RSTR + 12 + qc];
                    afr[1][mt][3] = Au[(r + 8) * RSTR + 12 + qc];
                }
                #pragma unroll
                for (int nt = 0; nt < 8; nt++) {
                    int n = nb + nt * 8 + qr;
                    bfr[1][nt][0] = Bu[n * RSTR + 8 + qc];
                    bfr[1][nt][1] = Bu[n * RSTR + 12 + qc];
                }
            }
            #pragma unroll
            for (int mt = 0; mt < 4; mt++)
                #pragma unroll
                for (int nt = 0; nt < 8; nt++)
                    mma_f16(acc[mt][nt], afr[s][mt], bfr[s][nt]);
        }
    }

    // -------- epilogue --------
    #pragma unroll
    for (int mt = 0; mt < 4; mt++) {
        int rl0 = mb + mt * 16 + qr;
        int rl1 = rl0 + 8;
        if (MODE == 0) {
            int r0 = m0 + rl0, r1 = m0 + rl1;
            #pragma unroll
            for (int nt = 0; nt < 8; nt++) {
                int c = n0 + nb + nt * 8 + qc * 2;
                float v0 = fmaxf(acc[mt][nt][0], 0.f); v0 *= v0;
                float v1 = fmaxf(acc[mt][nt][1], 0.f); v1 *= v1;
                float v2 = fmaxf(acc[mt][nt][2], 0.f); v2 *= v2;
                float v3 = fmaxf(acc[mt][nt][3], 0.f); v3 *= v3;
                *(__half2*)&g_s1h[(size_t)r0 * Nn + c] = __floats2half2_rn(v0, v1);
                *(__half2*)&g_s1h[(size_t)r1 * Nn + c] = __floats2half2_rn(v2, v3);
            }
        } else if (MODE == 1) {
            int r0 = m0 + rl0, r1 = m0 + rl1;
            #pragma unroll
            for (int nt = 0; nt < 8; nt++) {
                int c = n0 + nb + nt * 8 + qc * 2;
                *(float2*)&Cglob[(size_t)r0 * Nn + c] = make_float2(acc[mt][nt][0], acc[mt][nt][1]);
                *(float2*)&Cglob[(size_t)r1 * Nn + c] = make_float2(acc[mt][nt][2], acc[mt][nt][3]);
            }
        } else if (MODE == 2) {
            bool va = (m0 + rl0) < ne, vb = (m0 + rl1) < ne;
            int tk0 = va ? g_tok[e * Tt + m0 + rl0] : 0;
            int tk1 = vb ? g_tok[e * Tt + m0 + rl1] : 0;
            float w0 = va ? g_combine[tk0 * Ee + e] : 0.f;
            float w1 = vb ? g_combine[tk1 * Ee + e] : 0.f;
            size_t cr0 = (size_t)(off_e + m0 + rl0) * DF;
            size_t cr1 = (size_t)(off_e + m0 + rl1) * DF;
            #pragma unroll
            for (int nt = 0; nt < 8; nt++) {
                int c = n0 + nb + nt * 8 + qc * 2;
                float v0 = fmaxf(acc[mt][nt][0], 0.f); v0 = v0 * v0 * w0;
                float v1 = fmaxf(acc[mt][nt][1], 0.f); v1 = v1 * v1 * w0;
                float v2 = fmaxf(acc[mt][nt][2], 0.f); v2 = v2 * v2 * w1;
                float v3 = fmaxf(acc[mt][nt][3], 0.f); v3 = v3 * v3 * w1;
                if (va) *(__half2*)&g_acth[cr0 + c] = __floats2half2_rn(v0, v1);
                if (vb) *(__half2*)&g_acth[cr1 + c] = __floats2half2_rn(v2, v3);
            }
        } else {  // MODE 3: vector atomic scatter into out
            bool va = (m0 + rl0) < ne, vb = (m0 + rl1) < ne;
            int tk0 = va ? g_tok[e * Tt + m0 + rl0] : 0;
            int tk1 = vb ? g_tok[e * Tt + m0 + rl1] : 0;
            #pragma unroll
            for (int nt = 0; nt < 8; nt++) {
                int c = n0 + nb + nt * 8 + qc * 2;
                if (va) red2(&Cglob[(size_t)tk0 * Hd + c], acc[mt][nt][0], acc[mt][nt][1]);
                if (vb) red2(&Cglob[(size_t)tk1 * Hd + c], acc[mt][nt][2], acc[mt][nt][3]);
            }
        }
    }
}

// ---------------- launch ----------------
extern "C" void kernel_launch(void* const* d_in, const int* in_sizes, int n_in,
                              void* d_out, int out_size) {
    const float* x     = (const float*)d_in[0];
    const float* rw    = (const float*)d_in[1];
    const float* rb    = (const float*)d_in[2];
    const float* w_up  = (const float*)d_in[3];
    const float* w_dn  = (const float*)d_in[4];
    const float* s_up  = (const float*)d_in[5];
    const float* s_dn  = (const float*)d_in[6];
    float* out = (float*)d_out;

    cudaFuncSetAttribute(gemm_kernel<0>, cudaFuncAttributeMaxDynamicSharedMemorySize, SMEM_BYTES);
    cudaFuncSetAttribute(gemm_kernel<1>, cudaFuncAttributeMaxDynamicSharedMemorySize, SMEM_BYTES);
    cudaFuncSetAttribute(gemm_kernel<2>, cudaFuncAttributeMaxDynamicSharedMemorySize, SMEM_BYTES);
    cudaFuncSetAttribute(gemm_kernel<3>, cudaFuncAttributeMaxDynamicSharedMemorySize, SMEM_BYTES);

    // pre-pass: fp16 conversions + weight transposes
    __half *wupt, *wdnt, *supt, *sdnt;
    cudaGetSymbolAddress((void**)&wupt, g_wupt);
    cudaGetSymbolAddress((void**)&wdnt, g_wdnt);
    cudaGetSymbolAddress((void**)&supt, g_supt);
    cudaGetSymbolAddress((void**)&sdnt, g_sdnt);

    cvt_x_kernel<<<(Tt * Hd / 4) / 256, 256>>>(x);
    transp_kernel<<<dim3(DF / 32, Hd / 32, Ee), dim3(32, 8)>>>(w_up, wupt, Hd, DF);
    transp_kernel<<<dim3(Hd / 32, DF / 32, Ee), dim3(32, 8)>>>(w_dn, wdnt, DF, Hd);
    transp_kernel<<<dim3(DS / 32, Hd / 32, 1),  dim3(32, 8)>>>(s_up, supt, Hd, DS);
    transp_kernel<<<dim3(Hd / 32, DS / 32, 1),  dim3(32, 8)>>>(s_dn, sdnt, DS, Hd);

    zero_cnt_kernel<<<1, 32>>>();
    router_kernel<<<Tt, 128>>>(x, rw, rb);
    offs_kernel<<<1, 32>>>();

    // routed up: per-expert gathered GEMM -> g_acth
    gemm_kernel<2><<<dim3(DF / BN, Tt / BM, Ee), NTHR, SMEM_BYTES>>>(nullptr);

    // shared expert
    gemm_kernel<0><<<dim3(DS / BN, Tt / BM, 1), NTHR, SMEM_BYTES>>>(nullptr);
    gemm_kernel<1><<<dim3(Hd / BN, Tt / BM, 1), NTHR, SMEM_BYTES>>>(out);

    // routed down: atomic scatter onto out (after shared wrote it)
    gemm_kernel<3><<<dim3(Hd / BN, Tt / BM, Ee), NTHR, SMEM_BYTES>>>(out);
}

// round 13
// speedup vs baseline: 1.8192x; 1.0414x over previous
#include <cuda_runtime.h>
#include <cuda_fp16.h>
#include <cstdint>

#define Tt   2048
#define Hd   2048
#define Ee   32
#define DF   1024
#define DS   4096
#define TOPK 6
#define NGROUP 8
#define GSZ  4
#define TKG  4
#define SCALEF 2.5f

// ---------------- static device scratch (no allocations allowed) ----------------
__device__ float g_combine[Tt * Ee];
__device__ int   g_cnt[Ee];
__device__ int   g_off[Ee];
__device__ int   g_tok[Ee * Tt];

__device__ __align__(16) __half g_xh  [(size_t)Tt * Hd];        // x in fp16 (k-major)
__device__ __align__(16) __half g_wupt[(size_t)Ee * DF * Hd];   // w_up^T  [E][DF][Hd]
__device__ __align__(16) __half g_wdnt[(size_t)Ee * Hd * DF];   // w_down^T[E][Hd][DF]
__device__ __align__(16) __half g_supt[(size_t)DS * Hd];        // shared_up^T  [DS][Hd]
__device__ __align__(16) __half g_sdnt[(size_t)Hd * DS];        // shared_down^T[Hd][DS]
__device__ __align__(16) __half g_s1h [(size_t)Tt * DS];        // shared intermediate fp16
__device__ __align__(16) __half g_acth[(size_t)Tt * TOPK * DF]; // routed act fp16

// ---------------- small kernels ----------------
__global__ void zero_cnt_kernel() {
    if (threadIdx.x < Ee) g_cnt[threadIdx.x] = 0;
}
__global__ void offs_kernel() {
    if (threadIdx.x == 0) {
        int r = 0;
        for (int e = 0; e < Ee; e++) { g_off[e] = r; r += g_cnt[e]; }
    }
}

// x fp32 -> fp16 (layout preserved, k-major)
__global__ void cvt_x_kernel(const float* __restrict__ x) {
    int i = blockIdx.x * 256 + threadIdx.x;          // one float4 per thread
    float4 v = ((const float4*)x)[i];
    __half2 h0 = __floats2half2_rn(v.x, v.y);
    __half2 h1 = __floats2half2_rn(v.z, v.w);
    uint2 u;
    u.x = *(uint32_t*)&h0; u.y = *(uint32_t*)&h1;
    ((uint2*)g_xh)[i] = u;
}

// W fp32 [K][N] (batched) -> Wt fp16 [N][K]
// v2: 64(k) x 32(n) tiles, float4 loads (128B/row), half2 stores (128B/warp-row).
__global__ __launch_bounds__(256)
void transp_kernel(const float* __restrict__ W, __half* __restrict__ Wt,
                   int K, int N) {
    __shared__ float tile[64][33];
    const int b = blockIdx.z;
    const float* Wb = W + (size_t)b * K * N;
    __half* Wtb = Wt + (size_t)b * K * N;
    const int k0 = blockIdx.y * 64, n0 = blockIdx.x * 32;
    const int tid = threadIdx.x;

    // load: 64 k-rows x 8 float4; thread i -> k = i/8 + 32j, n4 = (i%8)*4
    const int lk = tid >> 3, ln4 = (tid & 7) * 4;
    #pragma unroll
    for (int j = 0; j < 2; j++) {
        float4 v = *(const float4*)&Wb[(size_t)(k0 + lk + 32 * j) * N + n0 + ln4];
        tile[lk + 32 * j][ln4 + 0] = v.x;
        tile[lk + 32 * j][ln4 + 1] = v.y;
        tile[lk + 32 * j][ln4 + 2] = v.z;
        tile[lk + 32 * j][ln4 + 3] = v.w;
    }
    __syncthreads();

    // store: 32 n-rows x 32 half2; thread i -> n = i/32 + 8j, kpair = (i%32)*2
    const int sn = tid >> 5, skp = (tid & 31) * 2;
    #pragma unroll
    for (int j = 0; j < 4; j++) {
        int n = sn + 8 * j;
        __half2 h = __floats2half2_rn(tile[skp][n], tile[skp + 1][n]);
        *(__half2*)&Wtb[(size_t)(n0 + n) * K + k0 + skp] = h;
    }
}

// ---------------- router: one block (128 thr) per token (fp32, unchanged) ----------------
__global__ void router_kernel(const float* __restrict__ x,
                              const float* __restrict__ rw,
                              const float* __restrict__ rb) {
    __shared__ __align__(16) float xs[Hd];
    __shared__ float logits[Ee];
    const int t   = blockIdx.x;
    const int tid = threadIdx.x;
    const float* xt = x + (size_t)t * Hd;

    for (int i = tid; i < Hd / 4; i += 128)
        ((float4*)xs)[i] = ((const float4*)xt)[i];
    __syncthreads();

    const int lane = tid & 31, wid = tid >> 5;
    for (int ei = 0; ei < 8; ei++) {
        int e = wid * 8 + ei;
        const float4* wr = (const float4*)(rw + (size_t)e * Hd);
        float s = 0.f;
        for (int i = lane; i < Hd / 4; i += 32) {
            float4 a = ((const float4*)xs)[i];
            float4 b = wr[i];
            s += a.x * b.x + a.y * b.y + a.z * b.z + a.w * b.w;
        }
        #pragma unroll
        for (int o = 16; o; o >>= 1) s += __shfl_xor_sync(0xffffffffu, s, o);
        if (lane == 0) logits[e] = s;
    }
    __syncthreads();

    if (tid < Ee) g_combine[t * Ee + tid] = 0.f;
    __syncthreads();

    if (tid == 0) {
        float sc[Ee], sfc[Ee];
        for (int e = 0; e < Ee; e++) {
            float v = 1.f / (1.f + expf(-logits[e]));
            sc[e]  = v;
            sfc[e] = v + rb[e];
        }
        float gs[NGROUP];
        for (int g = 0; g < NGROUP; g++) {
            float m1 = -1e30f, m2 = -1e30f;
            for (int j = 0; j < GSZ; j++) {
                float v = sfc[g * GSZ + j];
                if (v > m1) { m2 = m1; m1 = v; }
                else if (v > m2) m2 = v;
            }
            gs[g] = m1 + m2;
        }
        bool gsel[NGROUP];
        for (int g = 0; g < NGROUP; g++) gsel[g] = false;
        for (int k = 0; k < TKG; k++) {
            int bi = -1; float bv = -1e30f;
            for (int g = 0; g < NGROUP; g++)
                if (!gsel[g] && gs[g] > bv) { bv = gs[g]; bi = g; }
            gsel[bi] = true;
        }
        float masked[Ee];
        for (int e = 0; e < Ee; e++) masked[e] = gsel[e / GSZ] ? sfc[e] : 0.0f;

        int   idx[TOPK]; float tw[TOPK]; float tsum = 0.f;
        for (int k = 0; k < TOPK; k++) {
            int bi = 0; float bv = -1e30f;
            for (int e = 0; e < Ee; e++)
                if (masked[e] > bv) { bv = masked[e]; bi = e; }
            masked[bi] = -1e30f;
            idx[k] = bi; tw[k] = sc[bi]; tsum += sc[bi];
        }
        float inv = SCALEF / (tsum + 1e-20f);
        for (int k = 0; k < TOPK; k++) {
            int e = idx[k];
            g_combine[t * Ee + e] = tw[k] * inv;
            int slot = atomicAdd(&g_cnt[e], 1);
            g_tok[e * Tt + slot] = t;
        }
    }
}

// ------- fp16 warp-mma GEMM: 128x128x32 block, 4 warps (64x64), m16n8k16, cp.async x3 -------
#define BM 128
#define BN 128
#define BK 32           // halves
#define STAGES 3
#define NTHR 128
#define RSTR 20         // u32 per smem row (16 data + 4 pad -> conflict-free frag reads)
#define ASTAGE (BM * RSTR)   // u32
#define BSTAGE (BN * RSTR)
#define SMEM_BYTES (STAGES * (ASTAGE + BSTAGE) * 4)   // 61440

__device__ __forceinline__ void mma_f16(float (&c)[4], const uint32_t (&a)[4],
                                        const uint32_t (&b)[2]) {
    asm volatile(
        "mma.sync.aligned.m16n8k16.row.col.f32.f16.f16.f32 "
        "{%0,%1,%2,%3}, {%4,%5,%6,%7}, {%8,%9}, {%0,%1,%2,%3};\n"
        : "+f"(c[0]), "+f"(c[1]), "+f"(c[2]), "+f"(c[3])
        : "r"(a[0]), "r"(a[1]), "r"(a[2]), "r"(a[3]), "r"(b[0]), "r"(b[1]));
}

__device__ __forceinline__ void cp16(uint32_t dst, const void* src, bool valid) {
    int sz = valid ? 16 : 0;
    asm volatile("cp.async.cg.shared.global [%0], [%1], 16, %2;\n"
                 :: "r"(dst), "l"(src), "r"(sz));
}
__device__ __forceinline__ void cp_commit() {
    asm volatile("cp.async.commit_group;\n");
}
__device__ __forceinline__ void cp_wait() {
    asm volatile("cp.async.wait_group %0;\n" :: "n"(STAGES - 2));
}

__device__ __forceinline__ void red2(float* p, float v0, float v1) {
    asm volatile("red.global.add.v2.f32 [%0], {%1,%2};\n" :: "l"(p), "f"(v0), "f"(v1));
}

// MODE 0: shared up   (A = xh,        B = g_supt,       C = g_s1h fp16, relu2)
// MODE 1: shared down (A = g_s1h,     B = g_sdnt,       C = out fp32)
// MODE 2: moe up      (A = xh gather, B = g_wupt[e],    C = g_acth fp16, relu2*combine)
// MODE 3: moe down    (A = g_acth,    B = g_wdnt[e],    C = out, atomic scatter)
template <int MODE>
__global__ __launch_bounds__(NTHR, 2)
void gemm_kernel(float* __restrict__ Cglob) {
    extern __shared__ uint32_t smem[];
    uint32_t* As = smem;
    uint32_t* Bs = smem + STAGES * ASTAGE;

    constexpr int Kk = (MODE == 1) ? DS : ((MODE == 3) ? DF : Hd);
    constexpr int Nn = (MODE == 0) ? DS : ((MODE == 2) ? DF : Hd);

    const int tid = threadIdx.x;
    const int e  = (MODE >= 2) ? blockIdx.z : 0;
    const int m0 = blockIdx.y * BM;
    const int n0 = blockIdx.x * BN;

    int ne = Tt, off_e = 0;
    const __half* Ah = (MODE == 1) ? g_s1h : ((MODE == 3) ? g_acth : g_xh);
    const __half* Bt;
    if (MODE == 0) Bt = g_supt;
    else if (MODE == 1) Bt = g_sdnt;
    else if (MODE == 2) Bt = g_wupt + (size_t)e * DF * Hd;
    else Bt = g_wdnt + (size_t)e * Hd * DF;

    if (MODE >= 2) {
        ne = g_cnt[e];
        if (m0 >= ne) return;
        off_e = g_off[e];
    }

    // ---- loader mapping (cp.async, 16B = 8 halves per chunk, 128 threads) ----
    const int lr = tid >> 2;            // 0..31
    const int lc = tid & 3;             // chunk within 32-half row
    const __half* aSrc[4];
    #pragma unroll
    for (int i = 0; i < 4; i++) {
        int r = m0 + lr + i * 32;
        int grow;
        if (MODE == 2)      grow = (r < ne) ? g_tok[e * Tt + r] : -1;
        else if (MODE == 3) grow = (r < ne) ? (off_e + r) : -1;
        else                grow = r;
        aSrc[i] = (grow >= 0) ? (Ah + (size_t)grow * Kk + lc * 8) : nullptr;
    }
    const __half* bSrc = Bt + (size_t)(n0 + lr) * Kk + lc * 8;

    const uint32_t aBase = (uint32_t)__cvta_generic_to_shared(As) + ((lr * RSTR + lc * 4) * 4);
    const uint32_t bBase = (uint32_t)__cvta_generic_to_shared(Bs) + ((lr * RSTR + lc * 4) * 4);

    auto issue = [&](int k0, int st) {   // k0 in halves
        uint32_t ad = aBase + st * (ASTAGE * 4);
        #pragma unroll
        for (int i = 0; i < 4; i++)
            cp16(ad + i * (32 * RSTR * 4),
                 aSrc[i] ? (aSrc[i] + k0) : Ah, aSrc[i] != nullptr);
        uint32_t bd = bBase + st * (BSTAGE * 4);
        #pragma unroll
        for (int i = 0; i < 4; i++)
            cp16(bd + i * (32 * RSTR * 4), bSrc + (size_t)i * 32 * Kk + k0, true);
        cp_commit();
    };

    // ---- warp tiling: 2(m) x 2(n) warps, 64x64 per warp ----
    const int lane = tid & 31, wid = tid >> 5;
    const int qr = lane >> 2, qc = lane & 3;
    const int mb = (wid & 1) * 64;
    const int nb = (wid >> 1) * 64;

    float acc[4][8][4];
    #pragma unroll
    for (int mt = 0; mt < 4; mt++)
        #pragma unroll
        for (int nt = 0; nt < 8; nt++)
            #pragma unroll
            for (int j = 0; j < 4; j++) acc[mt][nt][j] = 0.f;

    uint32_t afr[2][4][4], bfr[2][8][2];

    const int nk = Kk / BK;

    #pragma unroll
    for (int s = 0; s < STAGES - 1; s++) issue(s * BK, s);

    for (int kb = 0; kb < nk; kb++) {
        cp_wait();
        __syncthreads();   // single barrier per K-tile (3-stage rotation)

        if (kb + STAGES - 1 < nk) issue((kb + STAGES - 1) * BK, (kb + STAGES - 1) % STAGES);
        else                      cp_commit();   // keep group counts aligned

        const uint32_t* Au = As + (kb % STAGES) * ASTAGE;
        const uint32_t* Bu = Bs + (kb % STAGES) * BSTAGE;

        // k16 step 0 fragments (u32 cols qc / qc+4)
        #pragma unroll
        for (int mt = 0; mt < 4; mt++) {
            int r = mb + mt * 16 + qr;
            afr[0][mt][0] = Au[r * RSTR + qc];
            afr[0][mt][1] = Au[(r + 8) * RSTR + qc];
            afr[0][mt][2] = Au[r * RSTR + qc + 4];
            afr[0][mt][3] = Au[(r + 8) * RSTR + qc + 4];
        }
        #pragma unroll
        for (int nt = 0; nt < 8; nt++) {
            int n = nb + nt * 8 + qr;
            bfr[0][nt][0] = Bu[n * RSTR + qc];
            bfr[0][nt][1] = Bu[n * RSTR + qc + 4];
        }

        #pragma unroll
        for (int s = 0; s < 2; s++) {
            if (s == 0) {   // prefetch k16 step 1 (u32 cols 8+qc / 12+qc)
                #pragma unroll
                for (int mt = 0; mt < 4; mt++) {
                    int r = mb + mt * 16 + qr;
                    afr[1][mt][0] = Au[r * RSTR + 8 + qc];
                    afr[1][mt][1] = Au[(r + 8) * RSTR + 8 + qc];
                    afr[1][mt][2] = Au[r * RSTR + 12 + qc];
                    afr[1][mt][3] = Au[(r + 8) * RSTR + 12 + qc];
                }
                #pragma unroll
                for (int nt = 0; nt < 8; nt++) {
                    int n = nb + nt * 8 + qr;
                    bfr[1][nt][0] = Bu[n * RSTR + 8 + qc];
                    bfr[1][nt][1] = Bu[n * RSTR + 12 + qc];
                }
            }
            #pragma unroll
            for (int mt = 0; mt < 4; mt++)
                #pragma unroll
                for (int nt = 0; nt < 8; nt++)
                    mma_f16(acc[mt][nt], afr[s][mt], bfr[s][nt]);
        }
    }

    // -------- epilogue --------
    #pragma unroll
    for (int mt = 0; mt < 4; mt++) {
        int rl0 = mb + mt * 16 + qr;
        int rl1 = rl0 + 8;
        if (MODE == 0) {
            int r0 = m0 + rl0, r1 = m0 + rl1;
            #pragma unroll
            for (int nt = 0; nt < 8; nt++) {
                int c = n0 + nb + nt * 8 + qc * 2;
                float v0 = fmaxf(acc[mt][nt][0], 0.f); v0 *= v0;
                float v1 = fmaxf(acc[mt][nt][1], 0.f); v1 *= v1;
                float v2 = fmaxf(acc[mt][nt][2], 0.f); v2 *= v2;
                float v3 = fmaxf(acc[mt][nt][3], 0.f); v3 *= v3;
                *(__half2*)&g_s1h[(size_t)r0 * Nn + c] = __floats2half2_rn(v0, v1);
                *(__half2*)&g_s1h[(size_t)r1 * Nn + c] = __floats2half2_rn(v2, v3);
            }
        } else if (MODE == 1) {
            int r0 = m0 + rl0, r1 = m0 + rl1;
            #pragma unroll
            for (int nt = 0; nt < 8; nt++) {
                int c = n0 + nb + nt * 8 + qc * 2;
                *(float2*)&Cglob[(size_t)r0 * Nn + c] = make_float2(acc[mt][nt][0], acc[mt][nt][1]);
                *(float2*)&Cglob[(size_t)r1 * Nn + c] = make_float2(acc[mt][nt][2], acc[mt][nt][3]);
            }
        } else if (MODE == 2) {
            bool va = (m0 + rl0) < ne, vb = (m0 + rl1) < ne;
            int tk0 = va ? g_tok[e * Tt + m0 + rl0] : 0;
            int tk1 = vb ? g_tok[e * Tt + m0 + rl1] : 0;
            float w0 = va ? g_combine[tk0 * Ee + e] : 0.f;
            float w1 = vb ? g_combine[tk1 * Ee + e] : 0.f;
            size_t cr0 = (size_t)(off_e + m0 + rl0) * DF;
            size_t cr1 = (size_t)(off_e + m0 + rl1) * DF;
            #pragma unroll
            for (int nt = 0; nt < 8; nt++) {
                int c = n0 + nb + nt * 8 + qc * 2;
                float v0 = fmaxf(acc[mt][nt][0], 0.f); v0 = v0 * v0 * w0;
                float v1 = fmaxf(acc[mt][nt][1], 0.f); v1 = v1 * v1 * w0;
                float v2 = fmaxf(acc[mt][nt][2], 0.f); v2 = v2 * v2 * w1;
                float v3 = fmaxf(acc[mt][nt][3], 0.f); v3 = v3 * v3 * w1;
                if (va) *(__half2*)&g_acth[cr0 + c] = __floats2half2_rn(v0, v1);
                if (vb) *(__half2*)&g_acth[cr1 + c] = __floats2half2_rn(v2, v3);
            }
        } else {  // MODE 3: vector atomic scatter into out
            bool va = (m0 + rl0) < ne, vb = (m0 + rl1) < ne;
            int tk0 = va ? g_tok[e * Tt + m0 + rl0] : 0;
            int tk1 = vb ? g_tok[e * Tt + m0 + rl1] : 0;
            #pragma unroll
            for (int nt = 0; nt < 8; nt++) {
                int c = n0 + nb + nt * 8 + qc * 2;
                if (va) red2(&Cglob[(size_t)tk0 * Hd + c], acc[mt][nt][0], acc[mt][nt][1]);
                if (vb) red2(&Cglob[(size_t)tk1 * Hd + c], acc[mt][nt][2], acc[mt][nt][3]);
            }
        }
    }
}

// ---------------- launch ----------------
extern "C" void kernel_launch(void* const* d_in, const int* in_sizes, int n_in,
                              void* d_out, int out_size) {
    const float* x     = (const float*)d_in[0];
    const float* rw    = (const float*)d_in[1];
    const float* rb    = (const float*)d_in[2];
    const float* w_up  = (const float*)d_in[3];
    const float* w_dn  = (const float*)d_in[4];
    const float* s_up  = (const float*)d_in[5];
    const float* s_dn  = (const float*)d_in[6];
    float* out = (float*)d_out;

    cudaFuncSetAttribute(gemm_kernel<0>, cudaFuncAttributeMaxDynamicSharedMemorySize, SMEM_BYTES);
    cudaFuncSetAttribute(gemm_kernel<1>, cudaFuncAttributeMaxDynamicSharedMemorySize, SMEM_BYTES);
    cudaFuncSetAttribute(gemm_kernel<2>, cudaFuncAttributeMaxDynamicSharedMemorySize, SMEM_BYTES);
    cudaFuncSetAttribute(gemm_kernel<3>, cudaFuncAttributeMaxDynamicSharedMemorySize, SMEM_BYTES);

    // pre-pass: fp16 conversions + weight transposes
    __half *wupt, *wdnt, *supt, *sdnt;
    cudaGetSymbolAddress((void**)&wupt, g_wupt);
    cudaGetSymbolAddress((void**)&wdnt, g_wdnt);
    cudaGetSymbolAddress((void**)&supt, g_supt);
    cudaGetSymbolAddress((void**)&sdnt, g_sdnt);

    cvt_x_kernel<<<(Tt * Hd / 4) / 256, 256>>>(x);
    transp_kernel<<<dim3(DF / 32, Hd / 64, Ee), 256>>>(w_up, wupt, Hd, DF);
    transp_kernel<<<dim3(Hd / 32, DF / 64, Ee), 256>>>(w_dn, wdnt, DF, Hd);
    transp_kernel<<<dim3(DS / 32, Hd / 64, 1),  256>>>(s_up, supt, Hd, DS);
    transp_kernel<<<dim3(Hd / 32, DS / 64, 1),  256>>>(s_dn, sdnt, DS, Hd);

    zero_cnt_kernel<<<1, 32>>>();
    router_kernel<<<Tt, 128>>>(x, rw, rb);
    offs_kernel<<<1, 32>>>();

    // routed up: per-expert gathered GEMM -> g_acth
    gemm_kernel<2><<<dim3(DF / BN, Tt / BM, Ee), NTHR, SMEM_BYTES>>>(nullptr);

    // shared expert
    gemm_kernel<0><<<dim3(DS / BN, Tt / BM, 1), NTHR, SMEM_BYTES>>>(nullptr);
    gemm_kernel<1><<<dim3(Hd / BN, Tt / BM, 1), NTHR, SMEM_BYTES>>>(out);

    // routed down: atomic scatter onto out (after shared wrote it)
    gemm_kernel<3><<<dim3(Hd / BN, Tt / BM, Ee), NTHR, SMEM_BYTES>>>(out);
}